// round 1
// baseline (speedup 1.0000x reference)
#include <cuda_runtime.h>

// ---------------------------------------------------------------------------
// DummyGCN4: 4-layer GCN, output = h3[node 1] only.
// Strategy: backward-slice the dependence cone of node 1, then compute only
// the needed frontier at each layer. Edge list is scanned 7x (3 backward
// expansions + 4 forward aggregations); all dense math is tiny.
// ---------------------------------------------------------------------------

#define MAXN 50048
#define BMW  1568          // bitmap words, >= ceil(50000/32)
#define OUT_NODE 1

// Scratch (static __device__ allocations — no runtime allocs allowed)
__device__ unsigned g_B0[BMW], g_B1[BMW], g_B2[BMW];
__device__ int   g_list0[MAXN], g_list1[MAXN], g_list2[MAXN];
__device__ int   g_cnt0, g_cnt1, g_cnt2;
__device__ float g_agg0[MAXN];                     // layer0 agg (width 1)
__device__ float g_h0[(size_t)MAXN * 64];          // lrelu(agg0*W0+b0)
__device__ float g_agg1[(size_t)MAXN * 64];        // layer1 agg
__device__ float g_h1[(size_t)MAXN * 128];         // lrelu(agg1@W1+b1)
__device__ float g_x2[(size_t)MAXN * 64];          // h1@W2 (mult-first layer)
__device__ float g_agg2[(size_t)MAXN * 64];        // layer2 agg
__device__ float g_x3[MAXN];                       // h2@W3 (mult-first layer)
__device__ float g_acc;                            // final scalar agg

__device__ __forceinline__ float lrelu(float x) { return x >= 0.f ? x : 0.01f * x; }
__device__ __forceinline__ bool tb(const unsigned* b, int i) {
    return (b[i >> 5] >> (i & 31)) & 1u;
}

// ---------------- init: clear bitmaps/counters ----------------
__global__ void k_clear() {
    int t = blockIdx.x * blockDim.x + threadIdx.x;
    if (t < BMW) { g_B0[t] = 0; g_B1[t] = 0; g_B2[t] = 0; }
    if (t == 0) { g_cnt0 = 0; g_cnt1 = 0; g_cnt2 = 0; g_acc = 0.f; }
}

// ---------------- backward expansions ----------------
// B2 = {src : dst == OUT_NODE}; zero agg2 row on first insert
__global__ void k_expand32(const int* __restrict__ src, const int* __restrict__ dst, int E) {
    int e = blockIdx.x * blockDim.x + threadIdx.x;
    if (e >= E) return;
    if (dst[e] != OUT_NODE) return;
    int s = src[e];
    unsigned m = 1u << (s & 31);
    unsigned old = atomicOr(&g_B2[s >> 5], m);
    if (!(old & m)) {
        int p = atomicAdd(&g_cnt2, 1);
        g_list2[p] = s;
        float* a = &g_agg2[(size_t)s * 64];
        #pragma unroll
        for (int j = 0; j < 64; j++) a[j] = 0.f;
    }
}

// B1 = {src : dst in B2}; zero agg1 row on first insert
__global__ void k_expand21(const int* __restrict__ src, const int* __restrict__ dst, int E) {
    int e = blockIdx.x * blockDim.x + threadIdx.x;
    if (e >= E) return;
    int d = dst[e];
    if (!tb(g_B2, d)) return;
    int s = src[e];
    unsigned m = 1u << (s & 31);
    unsigned old = atomicOr(&g_B1[s >> 5], m);
    if (!(old & m)) {
        int p = atomicAdd(&g_cnt1, 1);
        g_list1[p] = s;
        float* a = &g_agg1[(size_t)s * 64];
        #pragma unroll
        for (int j = 0; j < 64; j++) a[j] = 0.f;
    }
}

// B0 = {src : dst in B1}; zero agg0 scalar on first insert
__global__ void k_expand10(const int* __restrict__ src, const int* __restrict__ dst, int E) {
    int e = blockIdx.x * blockDim.x + threadIdx.x;
    if (e >= E) return;
    int d = dst[e];
    if (!tb(g_B1, d)) return;
    int s = src[e];
    unsigned m = 1u << (s & 31);
    unsigned old = atomicOr(&g_B0[s >> 5], m);
    if (!(old & m)) {
        int p = atomicAdd(&g_cnt0, 1);
        g_list0[p] = s;
        g_agg0[s] = 0.f;
    }
}

// ---------------- forward layer 0 ----------------
// agg0[d] += in_feat[src] for dst in B0
__global__ void k_agg0(const int* __restrict__ src, const int* __restrict__ dst, int E,
                       const float* __restrict__ in_feat) {
    int e = blockIdx.x * blockDim.x + threadIdx.x;
    if (e >= E) return;
    int d = dst[e];
    if (!tb(g_B0, d)) return;
    atomicAdd(&g_agg0[d], in_feat[src[e]]);
}

// h0[v] = lrelu(agg0[v] * W0 + b0), v in list0.  64 threads/block, grid-stride.
__global__ void k_h0(const float* __restrict__ W0, const float* __restrict__ b0) {
    int j = threadIdx.x;            // 0..63
    int cnt = g_cnt0;
    for (int idx = blockIdx.x; idx < cnt; idx += gridDim.x) {
        int v = g_list0[idx];
        float y = g_agg0[v] * W0[j] + b0[j];
        g_h0[(size_t)v * 64 + j] = lrelu(y);
    }
}

// ---------------- forward layer 1 ----------------
// agg1[d][:] += h0[src][:] for dst in B1
__global__ void k_agg1(const int* __restrict__ src, const int* __restrict__ dst, int E) {
    int e = blockIdx.x * blockDim.x + threadIdx.x;
    if (e >= E) return;
    int d = dst[e];
    if (!tb(g_B1, d)) return;
    const float* h = &g_h0[(size_t)src[e] * 64];
    float* a = &g_agg1[(size_t)d * 64];
    #pragma unroll
    for (int j = 0; j < 64; j++) atomicAdd(&a[j], h[j]);
}

// h1[v] = lrelu(agg1[v] @ W1 + b1), W1 [64,128].  128 threads/block.
__global__ void k_h1(const float* __restrict__ W1, const float* __restrict__ b1) {
    __shared__ float sa[64];
    int j = threadIdx.x;            // 0..127
    int cnt = g_cnt1;
    for (int idx = blockIdx.x; idx < cnt; idx += gridDim.x) {
        int v = g_list1[idx];
        if (j < 64) sa[j] = g_agg1[(size_t)v * 64 + j];
        __syncthreads();
        float acc = b1[j];
        #pragma unroll
        for (int k = 0; k < 64; k++) acc += sa[k] * W1[k * 128 + j];
        g_h1[(size_t)v * 128 + j] = lrelu(acc);
        __syncthreads();
    }
}

// ---------------- forward layer 2 (multiply-first) ----------------
// x2[v] = h1[v] @ W2, W2 [128,64], v in list1.  64 threads/block.
__global__ void k_x2(const float* __restrict__ W2) {
    __shared__ float sh[128];
    int j = threadIdx.x;            // 0..63
    int cnt = g_cnt1;
    for (int idx = blockIdx.x; idx < cnt; idx += gridDim.x) {
        int v = g_list1[idx];
        sh[j]      = g_h1[(size_t)v * 128 + j];
        sh[j + 64] = g_h1[(size_t)v * 128 + j + 64];
        __syncthreads();
        float acc = 0.f;
        #pragma unroll
        for (int k = 0; k < 128; k++) acc += sh[k] * W2[k * 64 + j];
        g_x2[(size_t)v * 64 + j] = acc;
        __syncthreads();
    }
}

// agg2[d][:] += x2[src][:] for dst in B2
__global__ void k_agg2(const int* __restrict__ src, const int* __restrict__ dst, int E) {
    int e = blockIdx.x * blockDim.x + threadIdx.x;
    if (e >= E) return;
    int d = dst[e];
    if (!tb(g_B2, d)) return;
    const float* x = &g_x2[(size_t)src[e] * 64];
    float* a = &g_agg2[(size_t)d * 64];
    #pragma unroll
    for (int j = 0; j < 64; j++) atomicAdd(&a[j], x[j]);
}

// ---------------- forward layer 3 (multiply-first) ----------------
// h2[v] = lrelu(agg2[v] + b2); x3[v] = h2[v] . W3  (64-dot), v in list2.
__global__ void k_h2x3(const float* __restrict__ b2, const float* __restrict__ W3) {
    __shared__ float s2[2];
    int j = threadIdx.x;            // 0..63
    int cnt = g_cnt2;
    for (int idx = blockIdx.x; idx < cnt; idx += gridDim.x) {
        int v = g_list2[idx];
        float y = lrelu(g_agg2[(size_t)v * 64 + j] + b2[j]);
        float p = y * W3[j];
        #pragma unroll
        for (int o = 16; o; o >>= 1) p += __shfl_down_sync(0xffffffffu, p, o);
        if ((j & 31) == 0) s2[j >> 5] = p;
        __syncthreads();
        if (j == 0) g_x3[v] = s2[0] + s2[1];
        __syncthreads();
    }
}

// acc += x3[src] for dst == OUT_NODE
__global__ void k_final(const int* __restrict__ src, const int* __restrict__ dst, int E) {
    int e = blockIdx.x * blockDim.x + threadIdx.x;
    if (e >= E) return;
    if (dst[e] != OUT_NODE) return;
    atomicAdd(&g_acc, g_x3[src[e]]);
}

__global__ void k_out(const float* __restrict__ b3, float* __restrict__ out) {
    out[0] = lrelu(g_acc + b3[0]);
}

// ---------------------------------------------------------------------------
extern "C" void kernel_launch(void* const* d_in, const int* in_sizes, int n_in,
                              void* d_out, int out_size) {
    const float* in_feat = (const float*)d_in[0];
    const int*   src     = (const int*)  d_in[1];
    const int*   dst     = (const int*)  d_in[2];
    const float* W0 = (const float*)d_in[3];
    const float* b0 = (const float*)d_in[4];
    const float* W1 = (const float*)d_in[5];
    const float* b1 = (const float*)d_in[6];
    const float* W2 = (const float*)d_in[7];
    const float* b2 = (const float*)d_in[8];
    const float* W3 = (const float*)d_in[9];
    const float* b3 = (const float*)d_in[10];
    float* out = (float*)d_out;

    int E = in_sizes[1];
    int eb = (E + 255) / 256;

    k_clear<<<(BMW + 255) / 256, 256>>>();

    // backward slice
    k_expand32<<<eb, 256>>>(src, dst, E);
    k_expand21<<<eb, 256>>>(src, dst, E);
    k_expand10<<<eb, 256>>>(src, dst, E);

    // forward
    k_agg0<<<eb, 256>>>(src, dst, E, in_feat);
    k_h0<<<1024, 64>>>(W0, b0);
    k_agg1<<<eb, 256>>>(src, dst, E);
    k_h1<<<512, 128>>>(W1, b1);
    k_x2<<<512, 64>>>(W2);
    k_agg2<<<eb, 256>>>(src, dst, E);
    k_h2x3<<<256, 64>>>(b2, W3);
    k_final<<<eb, 256>>>(src, dst, E);
    k_out<<<1, 1>>>(b3, out);
}

// round 2
// speedup vs baseline: 1.2581x; 1.2581x over previous
#include <cuda_runtime.h>

// ---------------------------------------------------------------------------
// DummyGCN4: 4-layer GCN, output = h3[node 1] only.
// R2: backward-slice + edge-list capture. Only 4 full edge scans remain
// (scan32, scan21, scan10, agg0), each vectorized int4 (4 edges/thread) for
// MLP. Matching edges are recorded during the backward scans so the forward
// aggregations for layers 1/2/3 run on compact edge lists (~16..4k edges).
// ---------------------------------------------------------------------------

#define MAXN 50048
#define BMW  1568
#define OUT_NODE 1
#define E1CAP  16384      // edges with dst == OUT_NODE
#define E2CAP  65536      // edges with dst in B2
#define E1BCAP 262144     // edges with dst in B1

__device__ unsigned g_B0[BMW], g_B1[BMW], g_B2[BMW];
__device__ int   g_list0[MAXN], g_list1[MAXN], g_list2[MAXN];
__device__ int   g_cnt0, g_cnt1, g_cnt2;
__device__ int   g_e1s[E1CAP];               __device__ int g_e1n;
__device__ int   g_e2s[E2CAP],  g_e2d[E2CAP];  __device__ int g_e2n;
__device__ int   g_ebs[E1BCAP], g_ebd[E1BCAP]; __device__ int g_ebn;
__device__ float g_agg0[MAXN];
__device__ float g_h0[(size_t)MAXN * 64];
__device__ float g_agg1[(size_t)MAXN * 64];
__device__ float g_h1[(size_t)MAXN * 128];
__device__ float g_x2[(size_t)MAXN * 64];
__device__ float g_agg2[(size_t)MAXN * 64];
__device__ float g_x3[MAXN];

__device__ __forceinline__ float lrelu(float x) { return x >= 0.f ? x : 0.01f * x; }
__device__ __forceinline__ bool tb(const unsigned* b, int i) {
    return (b[i >> 5] >> (i & 31)) & 1u;
}
__device__ __forceinline__ void zero64(float* a) {
    float4 z = make_float4(0.f, 0.f, 0.f, 0.f);
    float4* a4 = (float4*)a;
    #pragma unroll
    for (int j = 0; j < 16; j++) a4[j] = z;
}

// ---------------- init ----------------
__global__ void k_clear() {
    int t = blockIdx.x * blockDim.x + threadIdx.x;
    if (t < BMW) { g_B0[t] = 0; g_B1[t] = 0; g_B2[t] = 0; }
    if (t == 0) { g_cnt0 = 0; g_cnt1 = 0; g_cnt2 = 0; g_e1n = 0; g_e2n = 0; g_ebn = 0; }
}

// ---------------- scan 1: dst == OUT_NODE ----------------
__device__ __forceinline__ void hit32(const int* __restrict__ src, int e) {
    int s = src[e];
    int p = atomicAdd(&g_e1n, 1);
    if (p < E1CAP) g_e1s[p] = s;
    unsigned m = 1u << (s & 31);
    unsigned old = atomicOr(&g_B2[s >> 5], m);
    if (!(old & m)) {
        int q = atomicAdd(&g_cnt2, 1);
        g_list2[q] = s;
        zero64(&g_agg2[(size_t)s * 64]);
    }
}
__global__ void k_scan32(const int* __restrict__ src, const int* __restrict__ dst, int E) {
    int t = blockIdx.x * blockDim.x + threadIdx.x;
    int base = t * 4;
    if (base + 3 < E) {
        int4 d4 = *(const int4*)(dst + base);
        if (d4.x == OUT_NODE) hit32(src, base + 0);
        if (d4.y == OUT_NODE) hit32(src, base + 1);
        if (d4.z == OUT_NODE) hit32(src, base + 2);
        if (d4.w == OUT_NODE) hit32(src, base + 3);
    } else {
        for (int e = base; e < E; e++) if (dst[e] == OUT_NODE) hit32(src, e);
    }
}

// ---------------- scan 2: dst in B2 ----------------
__device__ __forceinline__ void hit21(const int* __restrict__ src, int e, int d) {
    int s = src[e];
    int p = atomicAdd(&g_e2n, 1);
    if (p < E2CAP) { g_e2s[p] = s; g_e2d[p] = d; }
    unsigned m = 1u << (s & 31);
    unsigned old = atomicOr(&g_B1[s >> 5], m);
    if (!(old & m)) {
        int q = atomicAdd(&g_cnt1, 1);
        g_list1[q] = s;
        zero64(&g_agg1[(size_t)s * 64]);
    }
}
__global__ void k_scan21(const int* __restrict__ src, const int* __restrict__ dst, int E) {
    int t = blockIdx.x * blockDim.x + threadIdx.x;
    int base = t * 4;
    if (base + 3 < E) {
        int4 d4 = *(const int4*)(dst + base);
        if (tb(g_B2, d4.x)) hit21(src, base + 0, d4.x);
        if (tb(g_B2, d4.y)) hit21(src, base + 1, d4.y);
        if (tb(g_B2, d4.z)) hit21(src, base + 2, d4.z);
        if (tb(g_B2, d4.w)) hit21(src, base + 3, d4.w);
    } else {
        for (int e = base; e < E; e++) { int d = dst[e]; if (tb(g_B2, d)) hit21(src, e, d); }
    }
}

// ---------------- scan 3: dst in B1 ----------------
__device__ __forceinline__ void hit10(const int* __restrict__ src, int e, int d) {
    int s = src[e];
    int p = atomicAdd(&g_ebn, 1);
    if (p < E1BCAP) { g_ebs[p] = s; g_ebd[p] = d; }
    unsigned m = 1u << (s & 31);
    unsigned old = atomicOr(&g_B0[s >> 5], m);
    if (!(old & m)) {
        int q = atomicAdd(&g_cnt0, 1);
        g_list0[q] = s;
        g_agg0[s] = 0.f;
    }
}
__global__ void k_scan10(const int* __restrict__ src, const int* __restrict__ dst, int E) {
    int t = blockIdx.x * blockDim.x + threadIdx.x;
    int base = t * 4;
    if (base + 3 < E) {
        int4 d4 = *(const int4*)(dst + base);
        if (tb(g_B1, d4.x)) hit10(src, base + 0, d4.x);
        if (tb(g_B1, d4.y)) hit10(src, base + 1, d4.y);
        if (tb(g_B1, d4.z)) hit10(src, base + 2, d4.z);
        if (tb(g_B1, d4.w)) hit10(src, base + 3, d4.w);
    } else {
        for (int e = base; e < E; e++) { int d = dst[e]; if (tb(g_B1, d)) hit10(src, e, d); }
    }
}

// ---------------- scan 4: layer-0 aggregation (dst in B0) ----------------
__global__ void k_agg0(const int* __restrict__ src, const int* __restrict__ dst, int E,
                       const float* __restrict__ in_feat) {
    int t = blockIdx.x * blockDim.x + threadIdx.x;
    int base = t * 4;
    if (base + 3 < E) {
        int4 d4 = *(const int4*)(dst + base);
        if (tb(g_B0, d4.x)) atomicAdd(&g_agg0[d4.x], in_feat[src[base + 0]]);
        if (tb(g_B0, d4.y)) atomicAdd(&g_agg0[d4.y], in_feat[src[base + 1]]);
        if (tb(g_B0, d4.z)) atomicAdd(&g_agg0[d4.z], in_feat[src[base + 2]]);
        if (tb(g_B0, d4.w)) atomicAdd(&g_agg0[d4.w], in_feat[src[base + 3]]);
    } else {
        for (int e = base; e < E; e++) {
            int d = dst[e];
            if (tb(g_B0, d)) atomicAdd(&g_agg0[d], in_feat[src[e]]);
        }
    }
}

// h0[v] = lrelu(agg0[v] * W0 + b0), v in list0
__global__ void k_h0(const float* __restrict__ W0, const float* __restrict__ b0) {
    int j = threadIdx.x;            // 0..63
    int cnt = g_cnt0;
    for (int idx = blockIdx.x; idx < cnt; idx += gridDim.x) {
        int v = g_list0[idx];
        g_h0[(size_t)v * 64 + j] = lrelu(g_agg0[v] * W0[j] + b0[j]);
    }
}

// agg1[d][:] += h0[s][:] over compact edge list (warp per edge)
__global__ void k_agg1c() {
    int n = min(g_ebn, E1BCAP);
    int lane = threadIdx.x & 31;
    int warp = (blockIdx.x * blockDim.x + threadIdx.x) >> 5;
    int nw = (gridDim.x * blockDim.x) >> 5;
    for (int i = warp; i < n; i += nw) {
        int s = g_ebs[i], d = g_ebd[i];
        const float* h = &g_h0[(size_t)s * 64];
        float* a = &g_agg1[(size_t)d * 64];
        atomicAdd(&a[lane],      h[lane]);
        atomicAdd(&a[lane + 32], h[lane + 32]);
    }
}

// h1[v] = lrelu(agg1[v] @ W1 + b1), W1 [64,128]
__global__ void k_h1(const float* __restrict__ W1, const float* __restrict__ b1) {
    __shared__ float sa[64];
    int j = threadIdx.x;            // 0..127
    int cnt = g_cnt1;
    for (int idx = blockIdx.x; idx < cnt; idx += gridDim.x) {
        int v = g_list1[idx];
        if (j < 64) sa[j] = g_agg1[(size_t)v * 64 + j];
        __syncthreads();
        float acc = b1[j];
        #pragma unroll
        for (int k = 0; k < 64; k++) acc += sa[k] * W1[k * 128 + j];
        g_h1[(size_t)v * 128 + j] = lrelu(acc);
        __syncthreads();
    }
}

// x2[v] = h1[v] @ W2, W2 [128,64]
__global__ void k_x2(const float* __restrict__ W2) {
    __shared__ float sh[128];
    int j = threadIdx.x;            // 0..63
    int cnt = g_cnt1;
    for (int idx = blockIdx.x; idx < cnt; idx += gridDim.x) {
        int v = g_list1[idx];
        sh[j]      = g_h1[(size_t)v * 128 + j];
        sh[j + 64] = g_h1[(size_t)v * 128 + j + 64];
        __syncthreads();
        float acc = 0.f;
        #pragma unroll
        for (int k = 0; k < 128; k++) acc += sh[k] * W2[k * 64 + j];
        g_x2[(size_t)v * 64 + j] = acc;
        __syncthreads();
    }
}

// agg2[d][:] += x2[s][:] over compact edge list
__global__ void k_agg2c() {
    int n = min(g_e2n, E2CAP);
    int lane = threadIdx.x & 31;
    int warp = (blockIdx.x * blockDim.x + threadIdx.x) >> 5;
    int nw = (gridDim.x * blockDim.x) >> 5;
    for (int i = warp; i < n; i += nw) {
        int s = g_e2s[i], d = g_e2d[i];
        const float* x = &g_x2[(size_t)s * 64];
        float* a = &g_agg2[(size_t)d * 64];
        atomicAdd(&a[lane],      x[lane]);
        atomicAdd(&a[lane + 32], x[lane + 32]);
    }
}

// h2[v] = lrelu(agg2[v] + b2); x3[v] = h2[v] . W3
__global__ void k_h2x3(const float* __restrict__ b2, const float* __restrict__ W3) {
    __shared__ float s2[2];
    int j = threadIdx.x;            // 0..63
    int cnt = g_cnt2;
    for (int idx = blockIdx.x; idx < cnt; idx += gridDim.x) {
        int v = g_list2[idx];
        float y = lrelu(g_agg2[(size_t)v * 64 + j] + b2[j]);
        float p = y * W3[j];
        #pragma unroll
        for (int o = 16; o; o >>= 1) p += __shfl_down_sync(0xffffffffu, p, o);
        if ((j & 31) == 0) s2[j >> 5] = p;
        __syncthreads();
        if (j == 0) g_x3[v] = s2[0] + s2[1];
        __syncthreads();
    }
}

// out = lrelu(sum over node-1 in-edges of x3[src] + b3)
__global__ void k_out(const float* __restrict__ b3, float* __restrict__ out) {
    __shared__ float red[4];
    int n = min(g_e1n, E1CAP);
    float s = 0.f;
    for (int i = threadIdx.x; i < n; i += blockDim.x) s += g_x3[g_e1s[i]];
    #pragma unroll
    for (int o = 16; o; o >>= 1) s += __shfl_down_sync(0xffffffffu, s, o);
    if ((threadIdx.x & 31) == 0) red[threadIdx.x >> 5] = s;
    __syncthreads();
    if (threadIdx.x == 0) {
        float t = red[0] + red[1] + red[2] + red[3];
        out[0] = lrelu(t + b3[0]);
    }
}

// ---------------------------------------------------------------------------
extern "C" void kernel_launch(void* const* d_in, const int* in_sizes, int n_in,
                              void* d_out, int out_size) {
    const float* in_feat = (const float*)d_in[0];
    const int*   src     = (const int*)  d_in[1];
    const int*   dst     = (const int*)  d_in[2];
    const float* W0 = (const float*)d_in[3];
    const float* b0 = (const float*)d_in[4];
    const float* W1 = (const float*)d_in[5];
    const float* b1 = (const float*)d_in[6];
    const float* W2 = (const float*)d_in[7];
    const float* b2 = (const float*)d_in[8];
    const float* W3 = (const float*)d_in[9];
    const float* b3 = (const float*)d_in[10];
    float* out = (float*)d_out;

    int E = in_sizes[1];
    int T = (E + 3) / 4;                 // one thread per 4 edges
    int sb = (T + 255) / 256;

    k_clear<<<(BMW + 255) / 256, 256>>>();

    k_scan32<<<sb, 256>>>(src, dst, E);
    k_scan21<<<sb, 256>>>(src, dst, E);
    k_scan10<<<sb, 256>>>(src, dst, E);

    k_agg0<<<sb, 256>>>(src, dst, E, in_feat);
    k_h0<<<1024, 64>>>(W0, b0);
    k_agg1c<<<512, 256>>>();
    k_h1<<<512, 128>>>(W1, b1);
    k_x2<<<512, 64>>>(W2);
    k_agg2c<<<64, 256>>>();
    k_h2x3<<<32, 64>>>(b2, W3);
    k_out<<<1, 128>>>(b3, out);
}